// round 10
// baseline (speedup 1.0000x reference)
#include <cuda_runtime.h>
#include <cstdint>

#define NHEADS  20
#define NUM_EX  13
#define TPB     128
#define TILE    256              // 2 samples per thread

#define E_SIZE   3120            // E' floats: [h][idx][12]
#define W_SIZE   1281

// dynamic smem layout (bytes)
#define SM_F      0              // f tile   : 256*240 = 61440
#define SM_EV     61440          // e tile   : 256*80  = 20480
#define SM_E      81920          // E' table : 12480
#define SM_MBAR   94400
#define SM_TOTAL  94464

#define F_TILE_B  61440
#define E_TILE_B  20480
#define EP_B      12480

__device__ __align__(16) float g_e[E_SIZE];
__device__ float g_w[W_SIZE + 3];
__constant__ float c_w[W_SIZE + 3];

// ---------------- PTX helpers ----------------
__device__ __forceinline__ uint32_t smem_u32(const void* p) {
    uint32_t a;
    asm("{ .reg .u64 t; cvta.to.shared.u64 t, %1; cvt.u32.u64 %0, t; }" : "=r"(a) : "l"(p));
    return a;
}
__device__ __forceinline__ void mbar_init(uint32_t m, uint32_t cnt) {
    asm volatile("mbarrier.init.shared.b64 [%0], %1;" :: "r"(m), "r"(cnt) : "memory");
}
__device__ __forceinline__ void mbar_expect_tx(uint32_t m, uint32_t bytes) {
    asm volatile("mbarrier.arrive.expect_tx.shared.b64 _, [%0], %1;" :: "r"(m), "r"(bytes) : "memory");
}
__device__ __forceinline__ void bulk_g2s(uint32_t dst, const void* src, uint32_t bytes, uint32_t m) {
    asm volatile("cp.async.bulk.shared::cta.global.mbarrier::complete_tx::bytes [%0], [%1], %2, [%3];"
                 :: "r"(dst), "l"(src), "r"(bytes), "r"(m) : "memory");
}
__device__ __forceinline__ void mbar_wait(uint32_t m, uint32_t parity) {
    uint32_t done;
    asm volatile("{\n\t.reg .pred p;\n\t"
                 "mbarrier.try_wait.parity.acquire.cta.shared::cta.b64 p, [%1], %2;\n\t"
                 "selp.b32 %0, 1, 0, p;\n\t}"
                 : "=r"(done) : "r"(m), "r"(parity) : "memory");
    if (!done) {
        asm volatile("{\n\t.reg .pred P1;\n\t"
                     "WL_%=:\n\t"
                     "mbarrier.try_wait.parity.acquire.cta.shared::cta.b64 P1, [%0], %1, 0x989680;\n\t"
                     "@P1 bra.uni WD_%=;\n\t"
                     "bra.uni WL_%=;\n\t"
                     "WD_%=:\n\t}" :: "r"(m), "r"(parity) : "memory");
    }
}
__device__ __forceinline__ float ex2f(float x) { float r; asm("ex2.approx.f32 %0, %1;" : "=f"(r) : "f"(x)); return r; }
__device__ __forceinline__ float lg2f(float x) { float r; asm("lg2.approx.f32 %0, %1;" : "=f"(r) : "f"(x)); return r; }

// ---------------------------------------------------------------------------
// Prep: fold Wf/bf/emb/b1 into E'; fold leaky slopes into W2; Wo*ln2 at o=62.
// ---------------------------------------------------------------------------
__global__ void prep_kernel(const float* __restrict__ emb, const float* __restrict__ Wf,
                            const float* __restrict__ bf,  const float* __restrict__ W1,
                            const float* __restrict__ b1,  const float* __restrict__ W2,
                            const float* __restrict__ b2,  const float* __restrict__ Wo,
                            const float* __restrict__ bo) {
    int t = blockIdx.x * blockDim.x + threadIdx.x;
    if (t >= E_SIZE + W_SIZE) return;
    if (t < E_SIZE) {
        int j = t % 12; int r = t / 12; int idx = r % NUM_EX; int h = r / NUM_EX;
        float v = 0.0f;
        if (j < 10) {
            v = b1[h * 10 + j];
            #pragma unroll
            for (int c = 0; c < 3; c++) v += emb[idx * 3 + c] * W1[(h * 8 + c) * 10 + j];
            #pragma unroll
            for (int i = 0; i < 5; i++) v += bf[i] * W1[(h * 8 + 3 + i) * 10 + j];
        }
        g_e[t] = v;
        return;
    }
    int u = t - E_SIZE;
    float v = 0.0f;
    if (u < 1280) {
        int h = u / 64; int o = u % 64;
        if (o < 36) {
            int c = o / 12; int j = o % 12;
            if (j < 10) {
                #pragma unroll
                for (int i = 0; i < 5; i++) v += Wf[c * 5 + i] * W1[(h * 8 + 3 + i) * 10 + j];
            }
        } else if (o < 48) {
            int j = o - 36; if (j < 10) v = 0.505f * W2[h * 10 + j];
        } else if (o < 60) {
            int j = o - 48; if (j < 10) v = 0.495f * W2[h * 10 + j];
        } else if (o == 60) {
            v = b2[h];
        } else if (o == 61) {
            v = Wo[h];
        } else if (o == 62) {
            v = Wo[h] * 0.69314718056f;   // Wo * ln2 (softplus via lg2)
        }
    } else {
        v = bo[0];
    }
    g_w[u] = v;
}

__device__ __forceinline__ float fabs_bits(float x) {
    return __int_as_float(__float_as_int(x) & 0x7FFFFFFF);
}

// ---------------------------------------------------------------------------
// Main: 2 samples/thread (amortizes the explicit LDC/LDCU weight loads, which
// on Blackwell are discrete instructions ~= half of all issue slots).
// f/e/E' staged via cp.async.bulk; weights from __constant__.
// ---------------------------------------------------------------------------
__global__ __launch_bounds__(TPB) void airfit_kernel(const int* __restrict__ e,
                                                     const float* __restrict__ f,
                                                     float* __restrict__ out, int B) {
    extern __shared__ __align__(16) char smem[];
    float4* sF  = reinterpret_cast<float4*>(smem + SM_F);
    int4*   sEv = reinterpret_cast<int4*>(smem + SM_EV);
    float*  sE  = reinterpret_cast<float*>(smem + SM_E);
    const uint32_t mbar = smem_u32(smem + SM_MBAR);

    const int tid = threadIdx.x;
    const bool full = ((size_t)(blockIdx.x + 1)) * TILE <= (size_t)B;

    if (full) {
        if (tid == 0) mbar_init(mbar, 1);
        asm volatile("fence.proxy.async.shared::cta;" ::: "memory");
        __syncthreads();
        if (tid == 0) {
            mbar_expect_tx(mbar, F_TILE_B + E_TILE_B + EP_B);
            bulk_g2s(smem_u32(smem + SM_F),  f + (size_t)blockIdx.x * TILE * 60, F_TILE_B, mbar);
            bulk_g2s(smem_u32(smem + SM_EV), e + (size_t)blockIdx.x * TILE * 20, E_TILE_B, mbar);
            bulk_g2s(smem_u32(smem + SM_E),  g_e, EP_B, mbar);
        }
        mbar_wait(mbar, 0);
    } else {
        for (int i = tid; i < E_SIZE; i += TPB) sE[i] = g_e[i];
        __syncthreads();
    }

    const int s0 = blockIdx.x * TILE + tid;
    const int s1 = s0 + TPB;
    if (s0 >= B) return;
    const bool has1 = full || (s1 < B);
    const int s1c = has1 ? s1 : s0;

    const float4* myF0 = sF  + tid * 15;
    const float4* myF1 = sF  + (tid + TPB) * 15;
    const int4*   myE0 = sEv + tid * 5;
    const int4*   myE1 = sEv + (tid + TPB) * 5;
    const float4* fg0  = reinterpret_cast<const float4*>(f) + (size_t)s0  * 15;
    const float4* fg1  = reinterpret_cast<const float4*>(f) + (size_t)s1c * 15;
    const int4*   eg0  = reinterpret_cast<const int4*>(e)   + (size_t)s0  * 5;
    const int4*   eg1  = reinterpret_cast<const int4*>(e)   + (size_t)s1c * 5;

    float res0 = c_w[1280], res1 = res0;

    #pragma unroll
    for (int hg = 0; hg < 5; hg++) {
        float4 A0, A1, A2, B0, B1, B2; int4 ev0, ev1;
        if (full) {
            A0 = myF0[hg * 3 + 0]; A1 = myF0[hg * 3 + 1]; A2 = myF0[hg * 3 + 2];
            B0 = myF1[hg * 3 + 0]; B1 = myF1[hg * 3 + 1]; B2 = myF1[hg * 3 + 2];
            ev0 = myE0[hg]; ev1 = myE1[hg];
        } else {
            A0 = fg0[hg * 3 + 0]; A1 = fg0[hg * 3 + 1]; A2 = fg0[hg * 3 + 2];
            B0 = fg1[hg * 3 + 0]; B1 = fg1[hg * 3 + 1]; B2 = fg1[hg * 3 + 2];
            ev0 = eg0[hg]; ev1 = eg1[hg];
        }
        float ga[12] = {A0.x, A0.y, A0.z, A0.w, A1.x, A1.y, A1.z, A1.w, A2.x, A2.y, A2.z, A2.w};
        float gb[12] = {B0.x, B0.y, B0.z, B0.w, B1.x, B1.y, B1.z, B1.w, B2.x, B2.y, B2.z, B2.w};
        int ix0[4] = {ev0.x, ev0.y, ev0.z, ev0.w};
        int ix1[4] = {ev1.x, ev1.y, ev1.z, ev1.w};

        #pragma unroll
        for (int k = 0; k < 4; k++) {
            const int h = hg * 4 + k;
            const int wb = h * 64;

            const float* Er0 = &sE[(h * NUM_EX + ix0[k]) * 12];
            const float* Er1 = &sE[(h * NUM_EX + ix1[k]) * 12];
            float4 X0 = *reinterpret_cast<const float4*>(Er0);
            float4 X1 = *reinterpret_cast<const float4*>(Er0 + 4);
            float2 X2 = *reinterpret_cast<const float2*>(Er0 + 8);
            float4 Y0 = *reinterpret_cast<const float4*>(Er1);
            float4 Y1 = *reinterpret_cast<const float4*>(Er1 + 4);
            float2 Y2 = *reinterpret_cast<const float2*>(Er1 + 8);
            float a0[10] = {X0.x, X0.y, X0.z, X0.w, X1.x, X1.y, X1.z, X1.w, X2.x, X2.y};
            float a1[10] = {Y0.x, Y0.y, Y0.z, Y0.w, Y1.x, Y1.y, Y1.z, Y1.w, Y2.x, Y2.y};

            // + f(3) @ W1f(3x10): each weight load serves BOTH samples (CSE)
            #pragma unroll
            for (int c = 0; c < 3; c++) {
                float fv0 = ga[k * 3 + c];
                float fv1 = gb[k * 3 + c];
                #pragma unroll
                for (int j = 0; j < 10; j++) {
                    float w = c_w[wb + c * 12 + j];
                    a0[j] = fmaf(fv0, w, a0[j]);
                    a1[j] = fmaf(fv1, w, a1[j]);
                }
            }

            // leaky folded: d = b2 + sum a*(0.505 w2) + |a|*(0.495 w2)
            float d0 = c_w[wb + 60], d1 = d0;
            #pragma unroll
            for (int j = 0; j < 10; j++) {
                float wa = c_w[wb + 36 + j];
                float wbb = c_w[wb + 48 + j];
                d0 = fmaf(a0[j], wa, d0);
                d0 = fmaf(fabs_bits(a0[j]), wbb, d0);
                d1 = fmaf(a1[j], wa, d1);
                d1 = fmaf(fabs_bits(a1[j]), wbb, d1);
            }

            // softplus via ex2/lg2 with ln2 folded into WoLn2:
            // res += max(d,0)*Wo + lg2(1 + 2^(-|d|*log2e)) * (Wo*ln2)
            float wo = c_w[wb + 61];
            float woln2 = c_w[wb + 62];
            float m0 = fmaxf(d0, 0.0f);
            float m1 = fmaxf(d1, 0.0f);
            float z0 = ex2f(fabsf(d0) * -1.44269504089f);
            float z1 = ex2f(fabsf(d1) * -1.44269504089f);
            float l0 = lg2f(1.0f + z0);
            float l1 = lg2f(1.0f + z1);
            res0 = fmaf(m0, wo, res0);
            res0 = fmaf(l0, woln2, res0);
            res1 = fmaf(m1, wo, res1);
            res1 = fmaf(l1, woln2, res1);
        }
    }

    out[s0] = res0;
    if (has1) out[s1] = res1;
}

// ---------------------------------------------------------------------------
extern "C" void kernel_launch(void* const* d_in, const int* in_sizes, int n_in,
                              void* d_out, int out_size) {
    const int*   e   = (const int*)  d_in[0];
    const float* f   = (const float*)d_in[1];
    const float* emb = (const float*)d_in[2];
    const float* Wf  = (const float*)d_in[3];
    const float* bf  = (const float*)d_in[4];
    const float* W1  = (const float*)d_in[5];
    const float* b1  = (const float*)d_in[6];
    const float* W2  = (const float*)d_in[7];
    const float* b2  = (const float*)d_in[8];
    const float* Wo  = (const float*)d_in[9];
    const float* bo  = (const float*)d_in[10];
    float* out = (float*)d_out;
    int B = out_size;

    prep_kernel<<<(E_SIZE + W_SIZE + 255) / 256, 256>>>(emb, Wf, bf, W1, b1, W2, b2, Wo, bo);

    void* c_addr = nullptr;
    void* g_addr = nullptr;
    cudaGetSymbolAddress(&c_addr, c_w);
    cudaGetSymbolAddress(&g_addr, g_w);
    cudaMemcpyAsync(c_addr, g_addr, W_SIZE * sizeof(float), cudaMemcpyDeviceToDevice);

    static bool attr_set = false;
    if (!attr_set) {
        cudaFuncSetAttribute(airfit_kernel, cudaFuncAttributeMaxDynamicSharedMemorySize, SM_TOTAL);
        attr_set = true;
    }
    airfit_kernel<<<(B + TILE - 1) / TILE, TPB, SM_TOTAL>>>(e, f, out, B);
}